// round 9
// baseline (speedup 1.0000x reference)
#include <cuda_runtime.h>
#include <cuda_bf16.h>
#include <math.h>
#include <cstdint>

// Problem constants
#define BB 2
#define SS 2048
#define DD 2048
#define HH 16
#define DH 128

typedef __nv_bfloat16 bf16;
typedef __nv_bfloat162 bf162;

// ---------------------------------------------------------------------------
// Scratch (device globals — no allocation allowed)
// ---------------------------------------------------------------------------
__device__ float g_q[BB * SS * DD];
__device__ float g_k[BB * SS * DD];
__device__ float g_v[BB * SS * DD];
__device__ float g_lse[BB * HH * SS];

__device__ bf16 g_xhi[BB * SS * DD],  g_xlo[BB * SS * DD];
__device__ bf16 g_wqhi[DD * DD], g_wqlo[DD * DD];
__device__ bf16 g_wkhi[DD * DD], g_wklo[DD * DD];
__device__ bf16 g_wvhi[DD * DD], g_wvlo[DD * DD];
__device__ bf16 g_wohi[DD * DD], g_wolo[DD * DD];
__device__ bf16 g_qhi[BB * SS * DD], g_qlo[BB * SS * DD];
__device__ bf16 g_khi[BB * SS * DD], g_klo[BB * SS * DD];
__device__ bf16 g_ahi[BB * SS * DD], g_alo[BB * SS * DD];

// ---------------------------------------------------------------------------
// helpers
// ---------------------------------------------------------------------------
__device__ __forceinline__ uint32_t smem_to_u32(const void* smem_ptr) {
    uint32_t addr;
    asm("{ .reg .u64 tmp; cvta.to.shared.u64 tmp, %1; cvt.u32.u64 %0, tmp; }"
        : "=r"(addr) : "l"(smem_ptr));
    return addr;
}

__device__ __forceinline__ float ex2f(float x) {
    float r;
    asm("ex2.approx.f32 %0, %1;" : "=f"(r) : "f"(x));
    return r;
}

__device__ __forceinline__ void ldsm4(uint32_t& r0, uint32_t& r1,
                                      uint32_t& r2, uint32_t& r3,
                                      uint32_t addr) {
    asm volatile("ldmatrix.sync.aligned.m8n8.x4.shared.b16 {%0,%1,%2,%3}, [%4];"
                 : "=r"(r0), "=r"(r1), "=r"(r2), "=r"(r3) : "r"(addr));
}

__device__ __forceinline__ void mma16816(float* c, const uint32_t* a,
                                         const uint32_t* b) {
    asm volatile(
        "mma.sync.aligned.m16n8k16.row.col.f32.bf16.bf16.f32 "
        "{%0,%1,%2,%3}, {%4,%5,%6,%7}, {%8,%9}, {%0,%1,%2,%3};"
        : "+f"(c[0]), "+f"(c[1]), "+f"(c[2]), "+f"(c[3])
        : "r"(a[0]), "r"(a[1]), "r"(a[2]), "r"(a[3]), "r"(b[0]), "r"(b[1]));
}

#define CP16(dst, src) \
    asm volatile("cp.async.cg.shared.global [%0], [%1], 16;" \
                 :: "r"(dst), "l"(src))
#define CPCOMMIT() asm volatile("cp.async.commit_group;")
#define CPWAIT(N) asm volatile("cp.async.wait_group %0;" :: "n"(N))

__device__ __forceinline__ void split2(float a, float b, bf162& hi, bf162& lo) {
    hi = __floats2bfloat162_rn(a, b);
    float2 hf = __bfloat1622float2(hi);
    lo = __floats2bfloat162_rn(a - hf.x, b - hf.y);
}

// ---------------------------------------------------------------------------
// fp32 -> bf16 hi/lo split (one-shot pre-pack)
// ---------------------------------------------------------------------------
__global__ __launch_bounds__(256) void split_kernel(
    const float* __restrict__ src, bf16* __restrict__ hi,
    bf16* __restrict__ lo, int n4)
{
    int i = blockIdx.x * blockDim.x + threadIdx.x;
    if (i >= n4) return;
    float4 v = ((const float4*)src)[i];
    bf162 h01, h23, l01, l23;
    split2(v.x, v.y, h01, l01);
    split2(v.z, v.w, h23, l23);
    ((bf162*)hi)[i * 2]     = h01;
    ((bf162*)hi)[i * 2 + 1] = h23;
    ((bf162*)lo)[i * 2]     = l01;
    ((bf162*)lo)[i * 2 + 1] = l23;
}

// ---------------------------------------------------------------------------
// GEMM: C[M,N] = A[M,K] @ B[N,K]^T  (bf16 hi/lo in, fp32 out, 3-pass comp)
// CTA 128x128, BK=32, 256 thr, 8 warps (2Mx4N). cp.async 3-stage pipeline.
// blockIdx.z selects (B, C) operand set (fused QKV).
// ---------------------------------------------------------------------------
#define GSTRIDE 80
#define GT 10240
#define GSTAGE 40960
#define GEMM_SMEM (3 * GSTAGE)

__global__ __launch_bounds__(256, 1) void gemm_bf16x3(
    const bf16* __restrict__ Ahi, const bf16* __restrict__ Alo,
    const bf16* __restrict__ Bh0, const bf16* __restrict__ Bl0, float* C0,
    const bf16* __restrict__ Bh1, const bf16* __restrict__ Bl1, float* C1,
    const bf16* __restrict__ Bh2, const bf16* __restrict__ Bl2, float* C2,
    int M, int N, int K)
{
    extern __shared__ __align__(128) char sm[];
    const int tid = threadIdx.x;
    const int lane = tid & 31;
    const int wid = tid >> 5;
    const int wm = wid & 1;
    const int wn = wid >> 1;
    const uint32_t sbase = smem_to_u32(sm);

    const int z = blockIdx.z;
    const bf16* Bhi = (z == 0) ? Bh0 : (z == 1) ? Bh1 : Bh2;
    const bf16* Blo = (z == 0) ? Bl0 : (z == 1) ? Bl1 : Bl2;
    float* C = (z == 0) ? C0 : (z == 1) ? C1 : C2;

    const bf16* Ah = Ahi + (size_t)blockIdx.y * 128 * K;
    const bf16* Al = Alo + (size_t)blockIdx.y * 128 * K;
    const bf16* Bh = Bhi + (size_t)blockIdx.x * 128 * K;
    const bf16* Bl = Blo + (size_t)blockIdx.x * 128 * K;

    auto stage_load = [&](int k0, int st) {
        uint32_t sb = sbase + st * GSTAGE;
#pragma unroll
        for (int t = 0; t < 8; t++) {
            int idx = tid + t * 256;
            int tile = idx >> 9;
            int within = idx & 511;
            int row = within >> 2;
            int cc = within & 3;
            const bf16* base = (tile == 0) ? Ah : (tile == 1) ? Al
                             : (tile == 2) ? Bh : Bl;
            const bf16* src = base + (size_t)row * K + k0 + cc * 8;
            CP16(sb + tile * GT + row * GSTRIDE + cc * 16, src);
        }
    };

    float c[4][4][4];
#pragma unroll
    for (int i = 0; i < 4; i++)
#pragma unroll
        for (int j = 0; j < 4; j++)
#pragma unroll
            for (int q = 0; q < 4; q++) c[i][j][q] = 0.f;

    const int a_r = wm * 64 + (lane & 7) + ((lane >> 3) & 1) * 8;
    const int a_kb = (lane >> 4) * 8;
    const int b_n = wn * 32 + (lane & 7) + (lane >> 4) * 8;
    const int b_kb = ((lane >> 3) & 1) * 8;

    stage_load(0, 0);
    CPCOMMIT();
    stage_load(32, 1);
    CPCOMMIT();

    const int nIter = K / 32;
    for (int it = 0; it < nIter; it++) {
        if (it + 2 < nIter) {
            stage_load((it + 2) * 32, (it + 2) % 3);
            CPCOMMIT();
            CPWAIT(2);
        } else {
            CPWAIT(0);
        }
        __syncthreads();

        uint32_t sb = sbase + (it % 3) * GSTAGE;
        uint32_t sa_hi = sb, sa_lo = sb + GT;
        uint32_t sb_hi = sb + 2 * GT, sb_lo = sb + 3 * GT;

#pragma unroll
        for (int ks = 0; ks < 2; ks++) {
            const int koff = (ks * 16 + a_kb) * 2;
            const int koffb = (ks * 16 + b_kb) * 2;
            uint32_t a[4][4], bh[2][4], bl[2][4];
#pragma unroll
            for (int mf = 0; mf < 4; mf++)
                ldsm4(a[mf][0], a[mf][1], a[mf][2], a[mf][3],
                      sa_hi + (a_r + mf * 16) * GSTRIDE + koff);
#pragma unroll
            for (int nf2 = 0; nf2 < 2; nf2++) {
                ldsm4(bh[nf2][0], bh[nf2][1], bh[nf2][2], bh[nf2][3],
                      sb_hi + (b_n + nf2 * 16) * GSTRIDE + koffb);
                ldsm4(bl[nf2][0], bl[nf2][1], bl[nf2][2], bl[nf2][3],
                      sb_lo + (b_n + nf2 * 16) * GSTRIDE + koffb);
            }
            // pass 1: hi*hi (16 independent c-frags between accum reuse)
#pragma unroll
            for (int mf = 0; mf < 4; mf++)
#pragma unroll
                for (int nf = 0; nf < 4; nf++)
                    mma16816(c[mf][nf], a[mf], &bh[nf >> 1][(nf & 1) * 2]);
            // pass 2: hi*lo
#pragma unroll
            for (int mf = 0; mf < 4; mf++)
#pragma unroll
                for (int nf = 0; nf < 4; nf++)
                    mma16816(c[mf][nf], a[mf], &bl[nf >> 1][(nf & 1) * 2]);
            // pass 3: lo*hi
#pragma unroll
            for (int mf = 0; mf < 4; mf++)
                ldsm4(a[mf][0], a[mf][1], a[mf][2], a[mf][3],
                      sa_lo + (a_r + mf * 16) * GSTRIDE + koff);
#pragma unroll
            for (int mf = 0; mf < 4; mf++)
#pragma unroll
                for (int nf = 0; nf < 4; nf++)
                    mma16816(c[mf][nf], a[mf], &bh[nf >> 1][(nf & 1) * 2]);
        }
        __syncthreads();
    }

    const int row0 = blockIdx.y * 128 + wm * 64 + (lane >> 2);
    const int col0 = blockIdx.x * 128 + wn * 32 + (lane & 3) * 2;
#pragma unroll
    for (int mf = 0; mf < 4; mf++)
#pragma unroll
        for (int nf = 0; nf < 4; nf++) {
            int r = row0 + mf * 16;
            int cc = col0 + nf * 8;
            *(float2*)(C + (size_t)r * N + cc) =
                make_float2(c[mf][nf][0], c[mf][nf][1]);
            *(float2*)(C + (size_t)(r + 8) * N + cc) =
                make_float2(c[mf][nf][2], c[mf][nf][3]);
        }
}

// ---------------------------------------------------------------------------
// RoPE + split: reads fp32 q/k, writes rotated bf16 hi/lo only.
// ---------------------------------------------------------------------------
__global__ __launch_bounds__(256) void rope_split(
    const float* __restrict__ q, const float* __restrict__ k,
    const float* __restrict__ cp, const float* __restrict__ sp,
    bf16* __restrict__ qhi, bf16* __restrict__ qlo,
    bf16* __restrict__ khi, bf16* __restrict__ klo)
{
    int idx = blockIdx.x * blockDim.x + threadIdx.x;
    if (idx >= BB * SS * HH * 64) return;
    int i = idx & 63;
    int h = (idx >> 6) & (HH - 1);
    int s = (idx >> 10) & (SS - 1);
    int b = idx >> 21;
    float c = cp[s * 64 + i];
    float sn = sp[s * 64 + i];
    size_t base = ((size_t)(b * SS + s)) * DD + h * DH + 2 * i;

    float qe = q[base], qo = q[base + 1];
    float qre = qe * c - qo * sn;
    float qim = qe * sn + qo * c;
    bf162 h2, l2;
    split2(qre, qim, h2, l2);
    *(bf162*)(qhi + base) = h2;
    *(bf162*)(qlo + base) = l2;

    float ke = k[base], ko = k[base + 1];
    float kre = ke * c - ko * sn;
    float kim = ke * sn + ko * c;
    split2(kre, kim, h2, l2);
    *(bf162*)(khi + base) = h2;
    *(bf162*)(klo + base) = l2;
}

// ---------------------------------------------------------------------------
// Flash LSE (bf16 hi/lo in): lse[b,h,s] = logsumexp_k( scale * q_s . k_k )
// CTA = (qtile 128, h, b). Q resident; K streamed 128-row tiles, cp.async x2.
// ---------------------------------------------------------------------------
#define FSTRIDE 272
#define FT 34816
#define FSTAGE (2 * FT)
#define FLASH_SMEM (2 * FT + 2 * FSTAGE)

__global__ __launch_bounds__(256, 1) void flash_lse_mma(
    const bf16* __restrict__ qhi, const bf16* __restrict__ qlo,
    const bf16* __restrict__ khi, const bf16* __restrict__ klo,
    float* __restrict__ lse)
{
    extern __shared__ __align__(128) char sm[];
    const int tid = threadIdx.x;
    const int lane = tid & 31;
    const int wid = tid >> 5;
    const int wm = wid & 1;
    const int wn = wid >> 1;
    const int qt = blockIdx.x, h = blockIdx.y, b = blockIdx.z;
    const uint32_t sbase = smem_to_u32(sm);
    const uint32_t sq_hi = sbase, sq_lo = sbase + FT;

    const float sc2 = 0.08838834764831845f * 1.4426950408889634f;

    const bf16* Qh = qhi + ((size_t)(b * SS + qt * 128)) * DD + h * DH;
    const bf16* Ql = qlo + ((size_t)(b * SS + qt * 128)) * DD + h * DH;

#pragma unroll
    for (int t = 0; t < 16; t++) {
        int idx = tid + t * 256;
        int tile = idx >> 11;
        int within = idx & 2047;
        int row = within >> 4;
        int cc = within & 15;
        const bf16* src = (tile ? Ql : Qh) + (size_t)row * DD + cc * 8;
        CP16(sbase + tile * FT + row * FSTRIDE + cc * 16, src);
    }

    auto kstage_load = [&](int kt, int st) {
        const bf16* Kh = khi + ((size_t)(b * SS + kt * 128)) * DD + h * DH;
        const bf16* Kl = klo + ((size_t)(b * SS + kt * 128)) * DD + h * DH;
        uint32_t sb = sbase + 2 * FT + st * FSTAGE;
#pragma unroll
        for (int t = 0; t < 16; t++) {
            int idx = tid + t * 256;
            int tile = idx >> 11;
            int within = idx & 2047;
            int row = within >> 4;
            int cc = within & 15;
            const bf16* src = (tile ? Kl : Kh) + (size_t)row * DD + cc * 8;
            CP16(sb + tile * FT + row * FSTRIDE + cc * 16, src);
        }
    };

    kstage_load(0, 0);
    CPCOMMIT();

    const int a_r = wm * 64 + (lane & 7) + ((lane >> 3) & 1) * 8;
    const int a_kb = (lane >> 4) * 8;
    const int b_n = wn * 32 + (lane & 7) + (lane >> 4) * 8;
    const int b_kb = ((lane >> 3) & 1) * 8;

    float m[8], l[8];
#pragma unroll
    for (int i = 0; i < 8; i++) { m[i] = -1e30f; l[i] = 0.f; }

    for (int kt = 0; kt < SS / 128; kt++) {
        if (kt + 1 < SS / 128) {
            kstage_load(kt + 1, (kt + 1) & 1);
            CPCOMMIT();
            CPWAIT(1);
        } else {
            CPWAIT(0);
        }
        __syncthreads();

        uint32_t sb = sbase + 2 * FT + (kt & 1) * FSTAGE;
        uint32_t sk_hi = sb, sk_lo = sb + FT;

        float c[4][4][4];
#pragma unroll
        for (int i = 0; i < 4; i++)
#pragma unroll
            for (int j = 0; j < 4; j++)
#pragma unroll
                for (int q = 0; q < 4; q++) c[i][j][q] = 0.f;

#pragma unroll
        for (int ks = 0; ks < 8; ks++) {
            const int koff = (ks * 16 + a_kb) * 2;
            const int koffb = (ks * 16 + b_kb) * 2;
            uint32_t a[4][4], bh[2][4], bl[2][4];
#pragma unroll
            for (int mf = 0; mf < 4; mf++)
                ldsm4(a[mf][0], a[mf][1], a[mf][2], a[mf][3],
                      sq_hi + (a_r + mf * 16) * FSTRIDE + koff);
#pragma unroll
            for (int nf2 = 0; nf2 < 2; nf2++) {
                ldsm4(bh[nf2][0], bh[nf2][1], bh[nf2][2], bh[nf2][3],
                      sk_hi + (b_n + nf2 * 16) * FSTRIDE + koffb);
                ldsm4(bl[nf2][0], bl[nf2][1], bl[nf2][2], bl[nf2][3],
                      sk_lo + (b_n + nf2 * 16) * FSTRIDE + koffb);
            }
            // pass 1: hi*hi
#pragma unroll
            for (int mf = 0; mf < 4; mf++)
#pragma unroll
                for (int nf = 0; nf < 4; nf++)
                    mma16816(c[mf][nf], a[mf], &bh[nf >> 1][(nf & 1) * 2]);
            // pass 2: hi*lo
#pragma unroll
            for (int mf = 0; mf < 4; mf++)
#pragma unroll
                for (int nf = 0; nf < 4; nf++)
                    mma16816(c[mf][nf], a[mf], &bl[nf >> 1][(nf & 1) * 2]);
            // pass 3: lo*hi
#pragma unroll
            for (int mf = 0; mf < 4; mf++)
                ldsm4(a[mf][0], a[mf][1], a[mf][2], a[mf][3],
                      sq_lo + (a_r + mf * 16) * FSTRIDE + koff);
#pragma unroll
            for (int mf = 0; mf < 4; mf++)
#pragma unroll
                for (int nf = 0; nf < 4; nf++)
                    mma16816(c[mf][nf], a[mf], &bh[nf >> 1][(nf & 1) * 2]);
        }

        // online (m, l) update, base-2 domain
#pragma unroll
        for (int mf = 0; mf < 4; mf++)
#pragma unroll
            for (int hf = 0; hf < 2; hf++) {
                int ri = mf * 2 + hf;
                float v[8];
#pragma unroll
                for (int nf = 0; nf < 4; nf++) {
                    v[nf * 2]     = c[mf][nf][hf * 2] * sc2;
                    v[nf * 2 + 1] = c[mf][nf][hf * 2 + 1] * sc2;
                }
                float mx = v[0];
#pragma unroll
                for (int j = 1; j < 8; j++) mx = fmaxf(mx, v[j]);
                mx = fmaxf(mx, __shfl_xor_sync(0xffffffffu, mx, 1));
                mx = fmaxf(mx, __shfl_xor_sync(0xffffffffu, mx, 2));
                float s = 0.f;
#pragma unroll
                for (int j = 0; j < 8; j++) s += ex2f(v[j] - mx);
                s += __shfl_xor_sync(0xffffffffu, s, 1);
                s += __shfl_xor_sync(0xffffffffu, s, 2);
                float mn = fmaxf(m[ri], mx);
                l[ri] = l[ri] * ex2f(m[ri] - mn) + s * ex2f(mx - mn);
                m[ri] = mn;
            }
        __syncthreads();
    }

    // cross-warp-stripe combine (4 n-stripes per row) via smem (reuse Q area)
    float2* red = (float2*)sm;   // [128][4]
    if ((lane & 3) == 0) {
#pragma unroll
        for (int mf = 0; mf < 4; mf++)
#pragma unroll
            for (int hf = 0; hf < 2; hf++) {
                int ri = mf * 2 + hf;
                int row = wm * 64 + mf * 16 + (lane >> 2) + hf * 8;
                red[row * 4 + wn] = make_float2(m[ri], l[ri]);
            }
    }
    __syncthreads();
    if (tid < 128) {
        float2 p0 = red[tid * 4 + 0], p1 = red[tid * 4 + 1];
        float2 p2 = red[tid * 4 + 2], p3 = red[tid * 4 + 3];
        float M = fmaxf(fmaxf(p0.x, p1.x), fmaxf(p2.x, p3.x));
        float L = p0.y * ex2f(p0.x - M) + p1.y * ex2f(p1.x - M) +
                  p2.y * ex2f(p2.x - M) + p3.y * ex2f(p3.x - M);
        lse[((size_t)(b * HH + h)) * SS + qt * 128 + tid] =
            (M + log2f(L)) * 0.6931471805599453f;
    }
}

// ---------------------------------------------------------------------------
// diag + scale: w = exp(scale*q.k - lse);  attn hi/lo = split(w * v)
// ---------------------------------------------------------------------------
__global__ __launch_bounds__(256) void diag_scale(
    const bf16* __restrict__ qhi, const bf16* __restrict__ qlo,
    const bf16* __restrict__ khi, const bf16* __restrict__ klo,
    const float* __restrict__ v, const float* __restrict__ lse,
    bf16* __restrict__ ahi, bf16* __restrict__ alo)
{
    int gw = (blockIdx.x * blockDim.x + threadIdx.x) >> 5;
    int lane = threadIdx.x & 31;
    if (gw >= BB * SS * HH) return;
    int h = gw & (HH - 1);
    int s = (gw >> 4) & (SS - 1);
    int b = gw >> 15;
    const float scale = 0.08838834764831845f;

    size_t base = ((size_t)(b * SS + s)) * DD + h * DH;
    float d = 0.f;
#pragma unroll
    for (int j = 0; j < 2; j++) {
        float2 qh = __bfloat1622float2(((const bf162*)(qhi + base))[lane * 2 + j]);
        float2 ql = __bfloat1622float2(((const bf162*)(qlo + base))[lane * 2 + j]);
        float2 kh = __bfloat1622float2(((const bf162*)(khi + base))[lane * 2 + j]);
        float2 kl = __bfloat1622float2(((const bf162*)(klo + base))[lane * 2 + j]);
        d += (qh.x + ql.x) * (kh.x + kl.x) + (qh.y + ql.y) * (kh.y + kl.y);
    }
#pragma unroll
    for (int o = 16; o > 0; o >>= 1) d += __shfl_xor_sync(0xffffffffu, d, o);
    float w = expf(d * scale - lse[((size_t)(b * HH + h)) * SS + s]);

    float4 vv = ((const float4*)(v + base))[lane];
    bf162 h01, h23, l01, l23;
    split2(vv.x * w, vv.y * w, h01, l01);
    split2(vv.z * w, vv.w * w, h23, l23);
    ((bf162*)(ahi + base))[lane * 2]     = h01;
    ((bf162*)(ahi + base))[lane * 2 + 1] = h23;
    ((bf162*)(alo + base))[lane * 2]     = l01;
    ((bf162*)(alo + base))[lane * 2 + 1] = l23;
}

// ---------------------------------------------------------------------------
extern "C" void kernel_launch(void* const* d_in, const int* in_sizes, int n_in,
                              void* d_out, int out_size)
{
    const float* x  = (const float*)d_in[0];
    const float* cp = (const float*)d_in[1];
    const float* sp = (const float*)d_in[2];
    const float* Wq = (const float*)d_in[3];
    const float* Wk = (const float*)d_in[4];
    const float* Wv = (const float*)d_in[5];
    const float* Wo = (const float*)d_in[6];
    float* out = (float*)d_out;

    float *gq, *gk, *gv, *gl;
    cudaGetSymbolAddress((void**)&gq, g_q);
    cudaGetSymbolAddress((void**)&gk, g_k);
    cudaGetSymbolAddress((void**)&gv, g_v);
    cudaGetSymbolAddress((void**)&gl, g_lse);

    bf16 *xhi, *xlo, *wqh, *wql, *wkh, *wkl, *wvh, *wvl, *woh, *wol;
    bf16 *qhi, *qlo, *khi, *klo, *ahi, *alo;
    cudaGetSymbolAddress((void**)&xhi, g_xhi);
    cudaGetSymbolAddress((void**)&xlo, g_xlo);
    cudaGetSymbolAddress((void**)&wqh, g_wqhi);
    cudaGetSymbolAddress((void**)&wql, g_wqlo);
    cudaGetSymbolAddress((void**)&wkh, g_wkhi);
    cudaGetSymbolAddress((void**)&wkl, g_wklo);
    cudaGetSymbolAddress((void**)&wvh, g_wvhi);
    cudaGetSymbolAddress((void**)&wvl, g_wvlo);
    cudaGetSymbolAddress((void**)&woh, g_wohi);
    cudaGetSymbolAddress((void**)&wol, g_wolo);
    cudaGetSymbolAddress((void**)&qhi, g_qhi);
    cudaGetSymbolAddress((void**)&qlo, g_qlo);
    cudaGetSymbolAddress((void**)&khi, g_khi);
    cudaGetSymbolAddress((void**)&klo, g_klo);
    cudaGetSymbolAddress((void**)&ahi, g_ahi);
    cudaGetSymbolAddress((void**)&alo, g_alo);

    cudaFuncSetAttribute(gemm_bf16x3,
        cudaFuncAttributeMaxDynamicSharedMemorySize, GEMM_SMEM);
    cudaFuncSetAttribute(flash_lse_mma,
        cudaFuncAttributeMaxDynamicSharedMemorySize, FLASH_SMEM);

    const int M = BB * SS;   // 4096
    const int NX4 = M * DD / 4;
    const int NW4 = DD * DD / 4;

    // pre-pack operands
    split_kernel<<<NX4 / 256, 256>>>(x, xhi, xlo, NX4);
    split_kernel<<<NW4 / 256, 256>>>(Wq, wqh, wql, NW4);
    split_kernel<<<NW4 / 256, 256>>>(Wk, wkh, wkl, NW4);
    split_kernel<<<NW4 / 256, 256>>>(Wv, wvh, wvl, NW4);
    split_kernel<<<NW4 / 256, 256>>>(Wo, woh, wol, NW4);

    // fused QKV projection (blockIdx.z selects weight/output)
    dim3 gqkv(DD / 128, M / 128, 3);
    gemm_bf16x3<<<gqkv, 256, GEMM_SMEM>>>(xhi, xlo,
        wqh, wql, gq, wkh, wkl, gk, wvh, wvl, gv, M, DD, DD);

    rope_split<<<(BB * SS * HH * 64) / 256, 256>>>(gq, gk, cp, sp,
                                                   qhi, qlo, khi, klo);

    flash_lse_mma<<<dim3(SS / 128, HH, BB), 256, FLASH_SMEM>>>(
        qhi, qlo, khi, klo, gl);

    diag_scale<<<(BB * SS * HH) / 8, 256>>>(qhi, qlo, khi, klo, gv, gl,
                                            ahi, alo);

    dim3 go(DD / 128, M / 128, 1);
    gemm_bf16x3<<<go, 256, GEMM_SMEM>>>(ahi, alo,
        woh, wol, out, woh, wol, out, woh, wol, out, M, DD, DD);
}

// round 13
// speedup vs baseline: 1.1353x; 1.1353x over previous
#include <cuda_runtime.h>
#include <cuda_bf16.h>
#include <math.h>
#include <cstdint>

// Problem constants
#define BB 2
#define SS 2048
#define DD 2048
#define HH 16
#define DH 128

typedef __nv_bfloat16 bf16;
typedef __nv_bfloat162 bf162;

// ---------------------------------------------------------------------------
// Scratch (device globals — no allocation allowed)
// ---------------------------------------------------------------------------
__device__ float g_q[BB * SS * DD];
__device__ float g_k[BB * SS * DD];
__device__ float g_v[BB * SS * DD];
__device__ float g_lse[BB * HH * SS];

__device__ bf16 g_xhi[BB * SS * DD],  g_xlo[BB * SS * DD];
__device__ bf16 g_wqhi[DD * DD], g_wqlo[DD * DD];
__device__ bf16 g_wkhi[DD * DD], g_wklo[DD * DD];
__device__ bf16 g_wvhi[DD * DD], g_wvlo[DD * DD];
__device__ bf16 g_wohi[DD * DD], g_wolo[DD * DD];
__device__ bf16 g_qhi[BB * SS * DD], g_qlo[BB * SS * DD];
__device__ bf16 g_khi[BB * SS * DD], g_klo[BB * SS * DD];
__device__ bf16 g_ahi[BB * SS * DD], g_alo[BB * SS * DD];

// ---------------------------------------------------------------------------
// helpers
// ---------------------------------------------------------------------------
__device__ __forceinline__ uint32_t smem_to_u32(const void* smem_ptr) {
    uint32_t addr;
    asm("{ .reg .u64 tmp; cvta.to.shared.u64 tmp, %1; cvt.u32.u64 %0, tmp; }"
        : "=r"(addr) : "l"(smem_ptr));
    return addr;
}

__device__ __forceinline__ float ex2f(float x) {
    float r;
    asm("ex2.approx.f32 %0, %1;" : "=f"(r) : "f"(x));
    return r;
}

__device__ __forceinline__ void ldsm4(uint32_t& r0, uint32_t& r1,
                                      uint32_t& r2, uint32_t& r3,
                                      uint32_t addr) {
    asm volatile("ldmatrix.sync.aligned.m8n8.x4.shared.b16 {%0,%1,%2,%3}, [%4];"
                 : "=r"(r0), "=r"(r1), "=r"(r2), "=r"(r3) : "r"(addr));
}

__device__ __forceinline__ void mma16816(float* c, const uint32_t* a,
                                         const uint32_t* b) {
    asm volatile(
        "mma.sync.aligned.m16n8k16.row.col.f32.bf16.bf16.f32 "
        "{%0,%1,%2,%3}, {%4,%5,%6,%7}, {%8,%9}, {%0,%1,%2,%3};"
        : "+f"(c[0]), "+f"(c[1]), "+f"(c[2]), "+f"(c[3])
        : "r"(a[0]), "r"(a[1]), "r"(a[2]), "r"(a[3]), "r"(b[0]), "r"(b[1]));
}

#define CP16(dst, src) \
    asm volatile("cp.async.cg.shared.global [%0], [%1], 16;" \
                 :: "r"(dst), "l"(src))
#define CPCOMMIT() asm volatile("cp.async.commit_group;")
#define CPWAIT(N) asm volatile("cp.async.wait_group %0;" :: "n"(N))

__device__ __forceinline__ void split2(float a, float b, bf162& hi, bf162& lo) {
    hi = __floats2bfloat162_rn(a, b);
    float2 hf = __bfloat1622float2(hi);
    lo = __floats2bfloat162_rn(a - hf.x, b - hf.y);
}

// ---------------------------------------------------------------------------
// fp32 -> bf16 hi/lo split. One launch handles x; another z-indexed launch
// handles the 4 weight matrices.
// ---------------------------------------------------------------------------
__device__ __forceinline__ void split_body(
    const float* __restrict__ src, bf16* __restrict__ hi,
    bf16* __restrict__ lo, int i)
{
    float4 v = ((const float4*)src)[i];
    bf162 h01, h23, l01, l23;
    split2(v.x, v.y, h01, l01);
    split2(v.z, v.w, h23, l23);
    ((bf162*)hi)[i * 2]     = h01;
    ((bf162*)hi)[i * 2 + 1] = h23;
    ((bf162*)lo)[i * 2]     = l01;
    ((bf162*)lo)[i * 2 + 1] = l23;
}

__global__ __launch_bounds__(256) void split_kernel(
    const float* __restrict__ src, bf16* __restrict__ hi,
    bf16* __restrict__ lo, int n4)
{
    int i = blockIdx.x * blockDim.x + threadIdx.x;
    if (i >= n4) return;
    split_body(src, hi, lo, i);
}

__global__ __launch_bounds__(256) void split_weights(
    const float* W0, bf16* h0, bf16* l0,
    const float* W1, bf16* h1, bf16* l1,
    const float* W2, bf16* h2, bf16* l2,
    const float* W3, bf16* h3, bf16* l3, int n4)
{
    int i = blockIdx.x * blockDim.x + threadIdx.x;
    if (i >= n4) return;
    int z = blockIdx.y;
    const float* src = (z == 0) ? W0 : (z == 1) ? W1 : (z == 2) ? W2 : W3;
    bf16* hi = (z == 0) ? h0 : (z == 1) ? h1 : (z == 2) ? h2 : h3;
    bf16* lo = (z == 0) ? l0 : (z == 1) ? l1 : (z == 2) ? l2 : l3;
    split_body(src, hi, lo, i);
}

// ---------------------------------------------------------------------------
// GEMM: C[M,N] = A[M,K] @ B[N,K]^T  (bf16 hi/lo in, fp32 out, 3-pass comp)
// CTA 128x128, BK=32, 256 thr, 8 warps (2Mx4N). cp.async double-buffered,
// 2 CTAs/SM. blockIdx.z selects (B, C) operand set (fused QKV).
// ---------------------------------------------------------------------------
#define GSTRIDE 80
#define GT 10240
#define GSTAGE 40960
#define GEMM_SMEM (2 * GSTAGE)

__global__ __launch_bounds__(256, 2) void gemm_bf16x3(
    const bf16* __restrict__ Ahi, const bf16* __restrict__ Alo,
    const bf16* __restrict__ Bh0, const bf16* __restrict__ Bl0, float* C0,
    const bf16* __restrict__ Bh1, const bf16* __restrict__ Bl1, float* C1,
    const bf16* __restrict__ Bh2, const bf16* __restrict__ Bl2, float* C2,
    int M, int N, int K)
{
    extern __shared__ __align__(128) char sm[];
    const int tid = threadIdx.x;
    const int lane = tid & 31;
    const int wid = tid >> 5;
    const int wm = wid & 1;
    const int wn = wid >> 1;
    const uint32_t sbase = smem_to_u32(sm);

    const int z = blockIdx.z;
    const bf16* Bhi = (z == 0) ? Bh0 : (z == 1) ? Bh1 : Bh2;
    const bf16* Blo = (z == 0) ? Bl0 : (z == 1) ? Bl1 : Bl2;
    float* C = (z == 0) ? C0 : (z == 1) ? C1 : C2;

    const bf16* Ah = Ahi + (size_t)blockIdx.y * 128 * K;
    const bf16* Al = Alo + (size_t)blockIdx.y * 128 * K;
    const bf16* Bh = Bhi + (size_t)blockIdx.x * 128 * K;
    const bf16* Bl = Blo + (size_t)blockIdx.x * 128 * K;

    auto stage_load = [&](int k0, int st) {
        uint32_t sb = sbase + st * GSTAGE;
#pragma unroll
        for (int t = 0; t < 8; t++) {
            int idx = tid + t * 256;
            int tile = idx >> 9;
            int within = idx & 511;
            int row = within >> 2;
            int cc = within & 3;
            const bf16* base = (tile == 0) ? Ah : (tile == 1) ? Al
                             : (tile == 2) ? Bh : Bl;
            const bf16* src = base + (size_t)row * K + k0 + cc * 8;
            CP16(sb + tile * GT + row * GSTRIDE + cc * 16, src);
        }
    };

    float c[4][4][4];
#pragma unroll
    for (int i = 0; i < 4; i++)
#pragma unroll
        for (int j = 0; j < 4; j++)
#pragma unroll
            for (int q = 0; q < 4; q++) c[i][j][q] = 0.f;

    const int a_r = wm * 64 + (lane & 7) + ((lane >> 3) & 1) * 8;
    const int a_kb = (lane >> 4) * 8;
    const int b_n = wn * 32 + (lane & 7) + (lane >> 4) * 8;
    const int b_kb = ((lane >> 3) & 1) * 8;

    stage_load(0, 0);
    CPCOMMIT();

    const int nIter = K / 32;
    for (int it = 0; it < nIter; it++) {
        if (it + 1 < nIter) {
            stage_load((it + 1) * 32, (it + 1) & 1);
            CPCOMMIT();
            CPWAIT(1);
        } else {
            CPWAIT(0);
        }
        __syncthreads();

        uint32_t sb = sbase + (it & 1) * GSTAGE;
        uint32_t sa_hi = sb, sa_lo = sb + GT;
        uint32_t sb_hi = sb + 2 * GT, sb_lo = sb + 3 * GT;

#pragma unroll
        for (int ks = 0; ks < 2; ks++) {
            const int koff = (ks * 16 + a_kb) * 2;
            const int koffb = (ks * 16 + b_kb) * 2;
            uint32_t a[4][4], bh[2][4], bl[2][4];
#pragma unroll
            for (int mf = 0; mf < 4; mf++)
                ldsm4(a[mf][0], a[mf][1], a[mf][2], a[mf][3],
                      sa_hi + (a_r + mf * 16) * GSTRIDE + koff);
#pragma unroll
            for (int nf2 = 0; nf2 < 2; nf2++) {
                ldsm4(bh[nf2][0], bh[nf2][1], bh[nf2][2], bh[nf2][3],
                      sb_hi + (b_n + nf2 * 16) * GSTRIDE + koffb);
                ldsm4(bl[nf2][0], bl[nf2][1], bl[nf2][2], bl[nf2][3],
                      sb_lo + (b_n + nf2 * 16) * GSTRIDE + koffb);
            }
            // pass 1: hi*hi  (16 independent c-frags between accum reuse)
#pragma unroll
            for (int mf = 0; mf < 4; mf++)
#pragma unroll
                for (int nf = 0; nf < 4; nf++)
                    mma16816(c[mf][nf], a[mf], &bh[nf >> 1][(nf & 1) * 2]);
            // pass 2: hi*lo
#pragma unroll
            for (int mf = 0; mf < 4; mf++)
#pragma unroll
                for (int nf = 0; nf < 4; nf++)
                    mma16816(c[mf][nf], a[mf], &bl[nf >> 1][(nf & 1) * 2]);
            // pass 3: lo*hi
#pragma unroll
            for (int mf = 0; mf < 4; mf++)
                ldsm4(a[mf][0], a[mf][1], a[mf][2], a[mf][3],
                      sa_lo + (a_r + mf * 16) * GSTRIDE + koff);
#pragma unroll
            for (int mf = 0; mf < 4; mf++)
#pragma unroll
                for (int nf = 0; nf < 4; nf++)
                    mma16816(c[mf][nf], a[mf], &bh[nf >> 1][(nf & 1) * 2]);
        }
        __syncthreads();
    }

    const int row0 = blockIdx.y * 128 + wm * 64 + (lane >> 2);
    const int col0 = blockIdx.x * 128 + wn * 32 + (lane & 3) * 2;
#pragma unroll
    for (int mf = 0; mf < 4; mf++)
#pragma unroll
        for (int nf = 0; nf < 4; nf++) {
            int r = row0 + mf * 16;
            int cc = col0 + nf * 8;
            *(float2*)(C + (size_t)r * N + cc) =
                make_float2(c[mf][nf][0], c[mf][nf][1]);
            *(float2*)(C + (size_t)(r + 8) * N + cc) =
                make_float2(c[mf][nf][2], c[mf][nf][3]);
        }
}

// ---------------------------------------------------------------------------
// RoPE + split: reads fp32 q/k, writes rotated bf16 hi/lo only.
// ---------------------------------------------------------------------------
__global__ __launch_bounds__(256) void rope_split(
    const float* __restrict__ q, const float* __restrict__ k,
    const float* __restrict__ cp, const float* __restrict__ sp,
    bf16* __restrict__ qhi, bf16* __restrict__ qlo,
    bf16* __restrict__ khi, bf16* __restrict__ klo)
{
    int idx = blockIdx.x * blockDim.x + threadIdx.x;
    if (idx >= BB * SS * HH * 64) return;
    int i = idx & 63;
    int h = (idx >> 6) & (HH - 1);
    int s = (idx >> 10) & (SS - 1);
    int b = idx >> 21;
    float c = cp[s * 64 + i];
    float sn = sp[s * 64 + i];
    size_t base = ((size_t)(b * SS + s)) * DD + h * DH + 2 * i;

    float qe = q[base], qo = q[base + 1];
    float qre = qe * c - qo * sn;
    float qim = qe * sn + qo * c;
    bf162 h2, l2;
    split2(qre, qim, h2, l2);
    *(bf162*)(qhi + base) = h2;
    *(bf162*)(qlo + base) = l2;

    float ke = k[base], ko = k[base + 1];
    float kre = ke * c - ko * sn;
    float kim = ke * sn + ko * c;
    split2(kre, kim, h2, l2);
    *(bf162*)(khi + base) = h2;
    *(bf162*)(klo + base) = l2;
}

// ---------------------------------------------------------------------------
// Flash LSE (bf16 hi/lo in): lse[b,h,s] = logsumexp_k( scale * q_s . k_k )
// CTA = (qtile 128, h, b). Q resident; K streamed 128-row tiles, cp.async x2.
// ---------------------------------------------------------------------------
#define FSTRIDE 272
#define FT 34816
#define FSTAGE (2 * FT)
#define FLASH_SMEM (2 * FT + 2 * FSTAGE)

__global__ __launch_bounds__(256, 1) void flash_lse_mma(
    const bf16* __restrict__ qhi, const bf16* __restrict__ qlo,
    const bf16* __restrict__ khi, const bf16* __restrict__ klo,
    float* __restrict__ lse)
{
    extern __shared__ __align__(128) char sm[];
    const int tid = threadIdx.x;
    const int lane = tid & 31;
    const int wid = tid >> 5;
    const int wm = wid & 1;
    const int wn = wid >> 1;
    const int qt = blockIdx.x, h = blockIdx.y, b = blockIdx.z;
    const uint32_t sbase = smem_to_u32(sm);
    const uint32_t sq_hi = sbase, sq_lo = sbase + FT;

    const float sc2 = 0.08838834764831845f * 1.4426950408889634f;

    const bf16* Qh = qhi + ((size_t)(b * SS + qt * 128)) * DD + h * DH;
    const bf16* Ql = qlo + ((size_t)(b * SS + qt * 128)) * DD + h * DH;

#pragma unroll
    for (int t = 0; t < 16; t++) {
        int idx = tid + t * 256;
        int tile = idx >> 11;
        int within = idx & 2047;
        int row = within >> 4;
        int cc = within & 15;
        const bf16* src = (tile ? Ql : Qh) + (size_t)row * DD + cc * 8;
        CP16(sbase + tile * FT + row * FSTRIDE + cc * 16, src);
    }

    auto kstage_load = [&](int kt, int st) {
        const bf16* Kh = khi + ((size_t)(b * SS + kt * 128)) * DD + h * DH;
        const bf16* Kl = klo + ((size_t)(b * SS + kt * 128)) * DD + h * DH;
        uint32_t sb = sbase + 2 * FT + st * FSTAGE;
#pragma unroll
        for (int t = 0; t < 16; t++) {
            int idx = tid + t * 256;
            int tile = idx >> 11;
            int within = idx & 2047;
            int row = within >> 4;
            int cc = within & 15;
            const bf16* src = (tile ? Kl : Kh) + (size_t)row * DD + cc * 8;
            CP16(sb + tile * FT + row * FSTRIDE + cc * 16, src);
        }
    };

    kstage_load(0, 0);
    CPCOMMIT();

    const int a_r = wm * 64 + (lane & 7) + ((lane >> 3) & 1) * 8;
    const int a_kb = (lane >> 4) * 8;
    const int b_n = wn * 32 + (lane & 7) + (lane >> 4) * 8;
    const int b_kb = ((lane >> 3) & 1) * 8;

    float m[8], l[8];
#pragma unroll
    for (int i = 0; i < 8; i++) { m[i] = -1e30f; l[i] = 0.f; }

    for (int kt = 0; kt < SS / 128; kt++) {
        if (kt + 1 < SS / 128) {
            kstage_load(kt + 1, (kt + 1) & 1);
            CPCOMMIT();
            CPWAIT(1);
        } else {
            CPWAIT(0);
        }
        __syncthreads();

        uint32_t sb = sbase + 2 * FT + (kt & 1) * FSTAGE;
        uint32_t sk_hi = sb, sk_lo = sb + FT;

        float c[4][4][4];
#pragma unroll
        for (int i = 0; i < 4; i++)
#pragma unroll
            for (int j = 0; j < 4; j++)
#pragma unroll
                for (int q = 0; q < 4; q++) c[i][j][q] = 0.f;

#pragma unroll
        for (int ks = 0; ks < 8; ks++) {
            const int koff = (ks * 16 + a_kb) * 2;
            const int koffb = (ks * 16 + b_kb) * 2;
            uint32_t a[4][4], bh[2][4], bl[2][4];
#pragma unroll
            for (int mf = 0; mf < 4; mf++)
                ldsm4(a[mf][0], a[mf][1], a[mf][2], a[mf][3],
                      sq_hi + (a_r + mf * 16) * FSTRIDE + koff);
#pragma unroll
            for (int nf2 = 0; nf2 < 2; nf2++) {
                ldsm4(bh[nf2][0], bh[nf2][1], bh[nf2][2], bh[nf2][3],
                      sk_hi + (b_n + nf2 * 16) * FSTRIDE + koffb);
                ldsm4(bl[nf2][0], bl[nf2][1], bl[nf2][2], bl[nf2][3],
                      sk_lo + (b_n + nf2 * 16) * FSTRIDE + koffb);
            }
            // pass 1: hi*hi
#pragma unroll
            for (int mf = 0; mf < 4; mf++)
#pragma unroll
                for (int nf = 0; nf < 4; nf++)
                    mma16816(c[mf][nf], a[mf], &bh[nf >> 1][(nf & 1) * 2]);
            // pass 2: hi*lo
#pragma unroll
            for (int mf = 0; mf < 4; mf++)
#pragma unroll
                for (int nf = 0; nf < 4; nf++)
                    mma16816(c[mf][nf], a[mf], &bl[nf >> 1][(nf & 1) * 2]);
            // pass 3: lo*hi
#pragma unroll
            for (int mf = 0; mf < 4; mf++)
                ldsm4(a[mf][0], a[mf][1], a[mf][2], a[mf][3],
                      sq_lo + (a_r + mf * 16) * FSTRIDE + koff);
#pragma unroll
            for (int mf = 0; mf < 4; mf++)
#pragma unroll
                for (int nf = 0; nf < 4; nf++)
                    mma16816(c[mf][nf], a[mf], &bh[nf >> 1][(nf & 1) * 2]);
        }

        // online (m, l) update, base-2 domain
#pragma unroll
        for (int mf = 0; mf < 4; mf++)
#pragma unroll
            for (int hf = 0; hf < 2; hf++) {
                int ri = mf * 2 + hf;
                float v[8];
#pragma unroll
                for (int nf = 0; nf < 4; nf++) {
                    v[nf * 2]     = c[mf][nf][hf * 2] * sc2;
                    v[nf * 2 + 1] = c[mf][nf][hf * 2 + 1] * sc2;
                }
                float mx = v[0];
#pragma unroll
                for (int j = 1; j < 8; j++) mx = fmaxf(mx, v[j]);
                mx = fmaxf(mx, __shfl_xor_sync(0xffffffffu, mx, 1));
                mx = fmaxf(mx, __shfl_xor_sync(0xffffffffu, mx, 2));
                float s = 0.f;
#pragma unroll
                for (int j = 0; j < 8; j++) s += ex2f(v[j] - mx);
                s += __shfl_xor_sync(0xffffffffu, s, 1);
                s += __shfl_xor_sync(0xffffffffu, s, 2);
                float mn = fmaxf(m[ri], mx);
                l[ri] = l[ri] * ex2f(m[ri] - mn) + s * ex2f(mx - mn);
                m[ri] = mn;
            }
        __syncthreads();
    }

    // cross-warp-stripe combine (4 n-stripes per row) via smem (reuse Q area)
    float2* red = (float2*)sm;   // [128][4]
    if ((lane & 3) == 0) {
#pragma unroll
        for (int mf = 0; mf < 4; mf++)
#pragma unroll
            for (int hf = 0; hf < 2; hf++) {
                int ri = mf * 2 + hf;
                int row = wm * 64 + mf * 16 + (lane >> 2) + hf * 8;
                red[row * 4 + wn] = make_float2(m[ri], l[ri]);
            }
    }
    __syncthreads();
    if (tid < 128) {
        float2 p0 = red[tid * 4 + 0], p1 = red[tid * 4 + 1];
        float2 p2 = red[tid * 4 + 2], p3 = red[tid * 4 + 3];
        float M = fmaxf(fmaxf(p0.x, p1.x), fmaxf(p2.x, p3.x));
        float L = p0.y * ex2f(p0.x - M) + p1.y * ex2f(p1.x - M) +
                  p2.y * ex2f(p2.x - M) + p3.y * ex2f(p3.x - M);
        lse[((size_t)(b * HH + h)) * SS + qt * 128 + tid] =
            (M + log2f(L)) * 0.6931471805599453f;
    }
}

// ---------------------------------------------------------------------------
// diag + scale: w = exp(scale*q.k - lse);  attn hi/lo = split(w * v)
// ---------------------------------------------------------------------------
__global__ __launch_bounds__(256) void diag_scale(
    const bf16* __restrict__ qhi, const bf16* __restrict__ qlo,
    const bf16* __restrict__ khi, const bf16* __restrict__ klo,
    const float* __restrict__ v, const float* __restrict__ lse,
    bf16* __restrict__ ahi, bf16* __restrict__ alo)
{
    int gw = (blockIdx.x * blockDim.x + threadIdx.x) >> 5;
    int lane = threadIdx.x & 31;
    if (gw >= BB * SS * HH) return;
    int h = gw & (HH - 1);
    int s = (gw >> 4) & (SS - 1);
    int b = gw >> 15;
    const float scale = 0.08838834764831845f;

    size_t base = ((size_t)(b * SS + s)) * DD + h * DH;
    float d = 0.f;
#pragma unroll
    for (int j = 0; j < 2; j++) {
        float2 qh = __bfloat1622float2(((const bf162*)(qhi + base))[lane * 2 + j]);
        float2 ql = __bfloat1622float2(((const bf162*)(qlo + base))[lane * 2 + j]);
        float2 kh = __bfloat1622float2(((const bf162*)(khi + base))[lane * 2 + j]);
        float2 kl = __bfloat1622float2(((const bf162*)(klo + base))[lane * 2 + j]);
        d += (qh.x + ql.x) * (kh.x + kl.x) + (qh.y + ql.y) * (kh.y + kl.y);
    }
#pragma unroll
    for (int o = 16; o > 0; o >>= 1) d += __shfl_xor_sync(0xffffffffu, d, o);
    float w = expf(d * scale - lse[((size_t)(b * HH + h)) * SS + s]);

    float4 vv = ((const float4*)(v + base))[lane];
    bf162 h01, h23, l01, l23;
    split2(vv.x * w, vv.y * w, h01, l01);
    split2(vv.z * w, vv.w * w, h23, l23);
    ((bf162*)(ahi + base))[lane * 2]     = h01;
    ((bf162*)(ahi + base))[lane * 2 + 1] = h23;
    ((bf162*)(alo + base))[lane * 2]     = l01;
    ((bf162*)(alo + base))[lane * 2 + 1] = l23;
}

// ---------------------------------------------------------------------------
extern "C" void kernel_launch(void* const* d_in, const int* in_sizes, int n_in,
                              void* d_out, int out_size)
{
    const float* x  = (const float*)d_in[0];
    const float* cp = (const float*)d_in[1];
    const float* sp = (const float*)d_in[2];
    const float* Wq = (const float*)d_in[3];
    const float* Wk = (const float*)d_in[4];
    const float* Wv = (const float*)d_in[5];
    const float* Wo = (const float*)d_in[6];
    float* out = (float*)d_out;

    float *gq, *gk, *gv, *gl;
    cudaGetSymbolAddress((void**)&gq, g_q);
    cudaGetSymbolAddress((void**)&gk, g_k);
    cudaGetSymbolAddress((void**)&gv, g_v);
    cudaGetSymbolAddress((void**)&gl, g_lse);

    bf16 *xhi, *xlo, *wqh, *wql, *wkh, *wkl, *wvh, *wvl, *woh, *wol;
    bf16 *qhi, *qlo, *khi, *klo, *ahi, *alo;
    cudaGetSymbolAddress((void**)&xhi, g_xhi);
    cudaGetSymbolAddress((void**)&xlo, g_xlo);
    cudaGetSymbolAddress((void**)&wqh, g_wqhi);
    cudaGetSymbolAddress((void**)&wql, g_wqlo);
    cudaGetSymbolAddress((void**)&wkh, g_wkhi);
    cudaGetSymbolAddress((void**)&wkl, g_wklo);
    cudaGetSymbolAddress((void**)&wvh, g_wvhi);
    cudaGetSymbolAddress((void**)&wvl, g_wvlo);
    cudaGetSymbolAddress((void**)&woh, g_wohi);
    cudaGetSymbolAddress((void**)&wol, g_wolo);
    cudaGetSymbolAddress((void**)&qhi, g_qhi);
    cudaGetSymbolAddress((void**)&qlo, g_qlo);
    cudaGetSymbolAddress((void**)&khi, g_khi);
    cudaGetSymbolAddress((void**)&klo, g_klo);
    cudaGetSymbolAddress((void**)&ahi, g_ahi);
    cudaGetSymbolAddress((void**)&alo, g_alo);

    cudaFuncSetAttribute(gemm_bf16x3,
        cudaFuncAttributeMaxDynamicSharedMemorySize, GEMM_SMEM);
    cudaFuncSetAttribute(flash_lse_mma,
        cudaFuncAttributeMaxDynamicSharedMemorySize, FLASH_SMEM);

    const int M = BB * SS;   // 4096
    const int NX4 = M * DD / 4;
    const int NW4 = DD * DD / 4;

    // pre-pack operands (x + all 4 weights in 2 launches)
    split_kernel<<<NX4 / 256, 256>>>(x, xhi, xlo, NX4);
    split_weights<<<dim3(NW4 / 256, 4), 256>>>(
        Wq, wqh, wql, Wk, wkh, wkl, Wv, wvh, wvl, Wo, woh, wol, NW4);

    // fused QKV projection (blockIdx.z selects weight/output)
    dim3 gqkv(DD / 128, M / 128, 3);
    gemm_bf16x3<<<gqkv, 256, GEMM_SMEM>>>(xhi, xlo,
        wqh, wql, gq, wkh, wkl, gk, wvh, wvl, gv, M, DD, DD);

    rope_split<<<(BB * SS * HH * 64) / 256, 256>>>(gq, gk, cp, sp,
                                                   qhi, qlo, khi, klo);

    flash_lse_mma<<<dim3(SS / 128, HH, BB), 256, FLASH_SMEM>>>(
        qhi, qlo, khi, klo, gl);

    diag_scale<<<(BB * SS * HH) / 8, 256>>>(qhi, qlo, khi, klo, gv, gl,
                                            ahi, alo);

    dim3 go(DD / 128, M / 128, 1);
    gemm_bf16x3<<<go, 256, GEMM_SMEM>>>(ahi, alo,
        woh, wol, out, woh, wol, out, woh, wol, out, M, DD, DD);
}